// round 4
// baseline (speedup 1.0000x reference)
#include <cuda_runtime.h>
#include <cuda_bf16.h>

// BSplineActivation: y = sum_i B_i^3(clip(x,-1,1)) * c_i, uniform 12-knot
// grid, 8 coefficients. Uniform knots => per interval j (0..10) the spline is
// one cubic in t. Bases+coefficients folded into an 11-entry cubic table,
// stored as two float2 arrays -> per-element gather is 2x conflict-free
// LDS.64 (11 float2 = 22 words < 32 banks). 16 elements/thread: 4
// front-batched LDG.128 (MLP=4), then compute+store per float4 immediately
// to keep live registers low (target <=48 regs, 5 CTAs/SM).

#define THREADS 256
#define VPT 4   // float4 per thread

__global__ void __launch_bounds__(THREADS, 5)
bspline_act_kernel(const float* __restrict__ x,
                   const float* __restrict__ grid,
                   const float* __restrict__ coef,
                   float* __restrict__ out,
                   int n4)
{
    __shared__ float2 sA[16];   // {P0,P1}
    __shared__ float2 sB[16];   // {P2,P3}
    __shared__ float  sInvH, sC;

    const int tid = threadIdx.x;

    if (tid < 16) {
        float c0 = 0.f, c1 = 0.f, c2 = 0.f, c3 = 0.f;
        if (tid < 11) {
            int i0 = tid - 3, i1 = tid - 2, i2 = tid - 1, i3 = tid;
            c0 = (i0 >= 0 && i0 < 8) ? __ldg(&coef[i0]) : 0.0f;
            c1 = (i1 >= 0 && i1 < 8) ? __ldg(&coef[i1]) : 0.0f;
            c2 = (i2 >= 0 && i2 < 8) ? __ldg(&coef[i2]) : 0.0f;
            c3 = (i3 >= 0 && i3 < 8) ? __ldg(&coef[i3]) : 0.0f;
        }
        float2 A, B;
        A.x = (c0 + 4.0f * c1 + c2) * (1.0f / 6.0f);          // P0
        A.y = (c2 - c0) * 0.5f;                               // P1
        B.x = (c0 - 2.0f * c1 + c2) * 0.5f;                   // P2
        B.y = (c3 - c0 + 3.0f * (c1 - c2)) * (1.0f / 6.0f);   // P3
        sA[tid] = A;
        sB[tid] = B;
        if (tid == 0) {
            float g0   = __ldg(&grid[0]);
            float g11  = __ldg(&grid[11]);
            float invh = 11.0f / (g11 - g0);
            sInvH = invh;
            sC    = -g0 * invh;
        }
    }
    __syncthreads();

    const float invh = sInvH;
    const float cadd = sC;

    const float4* __restrict__ x4 = (const float4*)x;
    float4* __restrict__ o4 = (float4*)out;

    const int base = blockIdx.x * (THREADS * VPT) + tid;

    // Front-batched loads: 4 independent LDG.128 in flight.
    float4 v[VPT];
    #pragma unroll
    for (int q = 0; q < VPT; q++) {
        int i = base + q * THREADS;
        if (i < n4) v[q] = x4[i];
    }

    // Compute + store per float4 immediately: low live-register count.
    #pragma unroll
    for (int q = 0; q < VPT; q++) {
        float4 r;
        #pragma unroll
        for (int k = 0; k < 4; k++) {
            float xv = (k == 0) ? v[q].x : (k == 1) ? v[q].y
                     : (k == 2) ? v[q].z : v[q].w;
            float xc = fminf(fmaxf(xv, -1.0f), 1.0f);
            float u  = fmaf(xc, invh, cadd);    // in (0.91, 10.09)
            int   j  = (int)u;                  // trunc == floor (u > 0)
            float t  = u - (float)j;
            float2 A = sA[j];
            float2 B = sB[j];
            float y  = fmaf(fmaf(fmaf(B.y, t, B.x), t, A.y), t, A.x);
            if (k == 0) r.x = y; else if (k == 1) r.y = y;
            else if (k == 2) r.z = y; else r.w = y;
        }
        int i = base + q * THREADS;
        if (i < n4) o4[i] = r;
    }
}

// Scalar tail kernel for n % 4 != 0 (not hit for 2048x4096).
__global__ void bspline_tail_kernel(const float* __restrict__ x,
                                    const float* __restrict__ grid,
                                    const float* __restrict__ coef,
                                    float* __restrict__ out,
                                    int start, int n)
{
    int idx = start + threadIdx.x;
    if (idx >= n) return;
    float g0  = grid[0];
    float invh = 11.0f / (grid[11] - g0);
    float xc = fminf(fmaxf(x[idx], -1.0f), 1.0f);
    float u  = (xc - g0) * invh;
    int   j  = min(max((int)u, 0), 10);
    float t  = u - (float)j;
    int i0 = j - 3, i1 = j - 2, i2 = j - 1, i3 = j;
    float c0 = (i0 >= 0 && i0 < 8) ? coef[i0] : 0.0f;
    float c1 = (i1 >= 0 && i1 < 8) ? coef[i1] : 0.0f;
    float c2 = (i2 >= 0 && i2 < 8) ? coef[i2] : 0.0f;
    float c3 = (i3 >= 0 && i3 < 8) ? coef[i3] : 0.0f;
    float p0 = (c0 + 4.0f * c1 + c2) * (1.0f / 6.0f);
    float p1 = (c2 - c0) * 0.5f;
    float p2 = (c0 - 2.0f * c1 + c2) * 0.5f;
    float p3 = (c3 - c0 + 3.0f * (c1 - c2)) * (1.0f / 6.0f);
    out[idx] = fmaf(fmaf(fmaf(p3, t, p2), t, p1), t, p0);
}

extern "C" void kernel_launch(void* const* d_in, const int* in_sizes, int n_in,
                              void* d_out, int out_size)
{
    const float* x    = (const float*)d_in[0];   // [2048*4096] fp32
    const float* grid = (const float*)d_in[1];   // [12] fp32
    const float* coef = (const float*)d_in[2];   // [8] fp32
    float* out = (float*)d_out;

    const int n  = in_sizes[0];
    const int n4 = n >> 2;

    int per_block = THREADS * VPT;
    int blocks = (n4 + per_block - 1) / per_block;
    if (blocks < 1) blocks = 1;

    bspline_act_kernel<<<blocks, THREADS>>>(x, grid, coef, out, n4);

    const int rem = n & 3;
    if (rem) {
        bspline_tail_kernel<<<1, 4>>>(x, grid, coef, out, n4 << 2, n);
    }
}